// round 8
// baseline (speedup 1.0000x reference)
#include <cuda_runtime.h>

// y = x * 2 + 3 over 67,108,864 fp32 (read-once/write-once stream).
// float4 x4 per thread, block-contiguous layout (each block streams one
// contiguous 64KB chunk), front-batched loads (MLP=4), evict-streaming hints.
//
// nvec = 16,777,216 float4; 8,192 blocks x 512 threads x 4 float4 = exact cover.

#define VPT 4      // float4 vectors per thread
#define TPB 512    // threads per block

__global__ __launch_bounds__(TPB) void fma_stream4c_kernel(
    const float4* __restrict__ in, float4* __restrict__ out)
{
    // Block-contiguous: block b owns [b*TPB*VPT, (b+1)*TPB*VPT)
    const unsigned base = blockIdx.x * (TPB * VPT) + threadIdx.x;

    float4 v[VPT];

    // Front-batch all 4 loads -> 4 outstanding LDG.128 per thread,
    // consecutive 2KB-aligned slabs within the block's 64KB chunk.
    #pragma unroll
    for (int i = 0; i < VPT; i++)
        v[i] = __ldcs(in + base + i * TPB);

    #pragma unroll
    for (int i = 0; i < VPT; i++) {
        v[i].x = fmaf(v[i].x, 2.0f, 3.0f);
        v[i].y = fmaf(v[i].y, 2.0f, 3.0f);
        v[i].z = fmaf(v[i].z, 2.0f, 3.0f);
        v[i].w = fmaf(v[i].w, 2.0f, 3.0f);
    }

    #pragma unroll
    for (int i = 0; i < VPT; i++)
        __stcs(out + base + i * TPB, v[i]);
}

extern "C" void kernel_launch(void* const* d_in, const int* in_sizes, int n_in,
                              void* d_out, int out_size) {
    const float4* in = (const float4*)d_in[0];
    float4* out = (float4*)d_out;
    const long long n    = (long long)in_sizes[0];   // 67,108,864
    const long long nvec = n / 4;                    // 16,777,216
    const int blocks = (int)(nvec / ((long long)TPB * VPT)); // 8,192
    fma_stream4c_kernel<<<blocks, TPB>>>(in, out);
}